// round 5
// baseline (speedup 1.0000x reference)
#include <cuda_runtime.h>
#include <cuda_bf16.h>
#include <cstdint>

// Problem dims (fixed by the dataset)
#define B_  64
#define T_  256
#define D_  512
#define H_  1024
#define M_  (B_ * T_)   // 16384

#define BK  32          // bf16 per k-tile (64 bytes per row)

// ---------------------------------------------------------------------------
// Scratch (__device__ globals; no allocations anywhere)
// ---------------------------------------------------------------------------
__device__ __nv_bfloat16 g_xs[3][(size_t)M_ * D_];  // x splits hi/mid/lo (48 MB)
__device__ __nv_bfloat16 g_ws[3][(size_t)H_ * D_];  // W_in splits (3 MB)
__device__ float g_pre[(size_t)M_ * H_];            // pre-activations (64 MB)
__device__ float g_part[256];

// ---------------------------------------------------------------------------
// Helpers (baseline-target PTX only: cp.async / ldmatrix / mma.sync)
// ---------------------------------------------------------------------------
__device__ __forceinline__ uint32_t smem_u32(const void* p) {
    uint32_t a;
    asm("{ .reg .u64 t; cvta.to.shared.u64 t, %1; cvt.u32.u64 %0, t; }"
        : "=r"(a) : "l"(p));
    return a;
}

__device__ __forceinline__ void cp_async16(uint32_t dst, const void* src) {
    asm volatile(
        "{ .reg .u64 g; cvta.to.global.u64 g, %1; "
        "cp.async.cg.shared.global [%0], [g], 16; }"
        :: "r"(dst), "l"(src) : "memory");
}
#define CP_COMMIT() asm volatile("cp.async.commit_group;" ::: "memory")
#define CP_WAIT0()  asm volatile("cp.async.wait_group 0;" ::: "memory")

// ---------------------------------------------------------------------------
// Kernel 0: 3-way bf16 split of x / W_in (hi + mid + lo ~= fp32 exactly)
// ---------------------------------------------------------------------------
__device__ __forceinline__ void split3(float x, __nv_bfloat16& h, __nv_bfloat16& m,
                                       __nv_bfloat16& l) {
    h = __float2bfloat16_rn(x);
    float r = x - __bfloat162float(h);
    m = __float2bfloat16_rn(r);
    float r2 = r - __bfloat162float(m);
    l = __float2bfloat16_rn(r2);
}

__global__ __launch_bounds__(256) void split_kernel(const float* __restrict__ src, int mode) {
    size_t i = ((size_t)blockIdx.x * blockDim.x + threadIdx.x) * 4;
    float4 v = *(const float4*)(src + i);
    __align__(8) __nv_bfloat16 h[4], m[4], l[4];
    split3(v.x, h[0], m[0], l[0]);
    split3(v.y, h[1], m[1], l[1]);
    split3(v.z, h[2], m[2], l[2]);
    split3(v.w, h[3], m[3], l[3]);
    if (mode == 0) {
        *(uint2*)&g_xs[0][i] = *(uint2*)h;
        *(uint2*)&g_xs[1][i] = *(uint2*)m;
        *(uint2*)&g_xs[2][i] = *(uint2*)l;
    } else {
        *(uint2*)&g_ws[0][i] = *(uint2*)h;
        *(uint2*)&g_ws[1][i] = *(uint2*)m;
        *(uint2*)&g_ws[2][i] = *(uint2*)l;
    }
}

// ---------------------------------------------------------------------------
// Kernel 1: bf16 mma.sync GEMM over K=6*512 (split-product accumulation).
// BM=128, BN=128, BK=32; 256 threads; warp tile 64x32 (m16n8k16).
// Segment s pairs: A in {hi,hi,mid,hi,mid,lo}, B in {hi,mid,hi,lo,mid,hi}
//   -> products hh, hm, mh, hl, mm, lh (dropped terms <= 2^-27 relative).
// ---------------------------------------------------------------------------
__global__ __launch_bounds__(256, 2) void mma_gemm_kernel(const float* __restrict__ bias) {
    __shared__ __align__(16) __nv_bfloat16 sA[2][128 * BK];
    __shared__ __align__(16) __nv_bfloat16 sB[2][128 * BK];
    __shared__ float s_bias[128];

    const int tid  = threadIdx.x;
    const int lane = tid & 31;
    const int w    = tid >> 5;
    const int wm   = (w >> 2) * 64;   // warp m-offset (2 warps along m)
    const int wn   = (w & 3) * 32;    // warp n-offset (4 warps along n)
    const int bm   = blockIdx.y * 128;
    const int bn   = blockIdx.x * 128;

    if (tid < 128) s_bias[tid] = bias[bn + tid];

    const uint32_t uA0 = smem_u32(sA[0]);
    const uint32_t uA1 = smem_u32(sA[1]);
    const uint32_t uB0 = smem_u32(sB[0]);
    const uint32_t uB1 = smem_u32(sB[1]);

    // cp.async mapping: tile = 128 rows x 64 B = 512 x 16B chunks; 2 per thread.
    // XOR swizzle: 16B-chunk column ^= (row & 3).
    const int r0 = tid >> 2;          // 0..63
    const int c0 = tid & 3;
    const int rA1 = r0 + 64;
    const uint32_t dOff0 = (uint32_t)r0  * 64u + (uint32_t)((c0 ^ (r0  & 3)) << 4);
    const uint32_t dOff1 = (uint32_t)rA1 * 64u + (uint32_t)((c0 ^ (rA1 & 3)) << 4);
    const int gcol = c0 * 8;          // element offset within k-tile

    float acc[4][4][4];
#pragma unroll
    for (int i = 0; i < 4; i++)
#pragma unroll
        for (int j = 0; j < 4; j++)
#pragma unroll
            for (int k = 0; k < 4; k++) acc[i][j][k] = 0.0f;

    // ldmatrix per-lane constants (row & 3 == lane & 3 for all our rows)
    const int baseRowA = wm + (lane & 7) + ((lane >> 3) & 1) * 8;
    const int chA_s0 = ((lane >> 4)) ^ (lane & 3);
    const int chA_s1 = (2 + (lane >> 4)) ^ (lane & 3);
    const int baseRowB = wn + (lane & 7);
    const int chB_s0 = (((lane >> 3) & 1)) ^ (lane & 3);
    const int chB_s1 = (2 + ((lane >> 3) & 1)) ^ (lane & 3);

    auto issue_tile = [&](int seg, int it, uint32_t ua, uint32_t ub) {
        const __nv_bfloat16* Ab =
            (seg == 2 || seg == 4) ? g_xs[1] : (seg == 5 ? g_xs[2] : g_xs[0]);
        const __nv_bfloat16* Bb =
            (seg == 1 || seg == 4) ? g_ws[1] : (seg == 3 ? g_ws[2] : g_ws[0]);
        const int k0 = it * BK + gcol;
        cp_async16(ua + dOff0, Ab + (size_t)(bm + r0)  * D_ + k0);
        cp_async16(ua + dOff1, Ab + (size_t)(bm + rA1) * D_ + k0);
        cp_async16(ub + dOff0, Bb + (size_t)(bn + r0)  * D_ + k0);
        cp_async16(ub + dOff1, Bb + (size_t)(bn + rA1) * D_ + k0);
    };

    auto compute = [&](uint32_t ua, uint32_t ub) {
#pragma unroll
        for (int step = 0; step < 2; ++step) {
            const int chA = step ? chA_s1 : chA_s0;
            const int chB = step ? chB_s1 : chB_s0;
            uint32_t a[4][4], b[4][2];
#pragma unroll
            for (int mi = 0; mi < 4; ++mi) {
                uint32_t addr = ua + (uint32_t)(baseRowA + mi * 16) * 64u
                                   + ((uint32_t)chA << 4);
                asm volatile(
                    "ldmatrix.sync.aligned.m8n8.x4.shared.b16 {%0,%1,%2,%3}, [%4];"
                    : "=r"(a[mi][0]), "=r"(a[mi][1]), "=r"(a[mi][2]), "=r"(a[mi][3])
                    : "r"(addr));
            }
#pragma unroll
            for (int ni = 0; ni < 4; ++ni) {
                uint32_t addr = ub + (uint32_t)(baseRowB + ni * 8) * 64u
                                   + ((uint32_t)chB << 4);
                asm volatile(
                    "ldmatrix.sync.aligned.m8n8.x2.shared.b16 {%0,%1}, [%2];"
                    : "=r"(b[ni][0]), "=r"(b[ni][1])
                    : "r"(addr));
            }
#pragma unroll
            for (int mi = 0; mi < 4; ++mi)
#pragma unroll
                for (int ni = 0; ni < 4; ++ni)
                    asm volatile(
                        "mma.sync.aligned.m16n8k16.row.col.f32.bf16.bf16.f32 "
                        "{%0,%1,%2,%3}, {%4,%5,%6,%7}, {%8,%9}, {%0,%1,%2,%3};"
                        : "+f"(acc[mi][ni][0]), "+f"(acc[mi][ni][1]),
                          "+f"(acc[mi][ni][2]), "+f"(acc[mi][ni][3])
                        : "r"(a[mi][0]), "r"(a[mi][1]), "r"(a[mi][2]), "r"(a[mi][3]),
                          "r"(b[ni][0]), "r"(b[ni][1]));
        }
    };

    // Prime buffer 0 with (seg=0, it=0)
    issue_tile(0, 0, uA0, uB0);
    CP_COMMIT();
    CP_WAIT0();
    __syncthreads();

    int buf = 0;
    for (int ks = 0; ks < 96; ++ks) {
        if (ks + 1 < 96) {
            const int nx = ks + 1;
            issue_tile(nx >> 4, nx & 15, buf ? uA0 : uA1, buf ? uB0 : uB1);
        }
        CP_COMMIT();
        compute(buf ? uA1 : uA0, buf ? uB1 : uB0);
        CP_WAIT0();
        __syncthreads();
        buf ^= 1;
    }

    // Epilogue: c-frag rows l>>2 (+8), cols (l&3)*2 (+1); add bias, store fp32
    const int mrow = lane >> 2;
    const int ncol = (lane & 3) * 2;
#pragma unroll
    for (int mi = 0; mi < 4; ++mi) {
        const int m0 = bm + wm + mi * 16 + mrow;
#pragma unroll
        for (int ni = 0; ni < 4; ++ni) {
            const int nc = wn + ni * 8 + ncol;
            const int n0 = bn + nc;
            float2 v0 = make_float2(acc[mi][ni][0] + s_bias[nc],
                                    acc[mi][ni][1] + s_bias[nc + 1]);
            float2 v1 = make_float2(acc[mi][ni][2] + s_bias[nc],
                                    acc[mi][ni][3] + s_bias[nc + 1]);
            *(float2*)&g_pre[(size_t)m0 * H_ + n0] = v0;
            *(float2*)&g_pre[(size_t)(m0 + 8) * H_ + n0] = v1;
        }
    }
}

// ---------------------------------------------------------------------------
// Kernel 2: ALIF recurrence + weighted partial reduce
// ---------------------------------------------------------------------------
__global__ __launch_bounds__(256) void alif_scan_kernel(const float* __restrict__ W_out) {
    const int b  = blockIdx.x >> 2;
    const int hc = blockIdx.x & 3;
    const int h  = hc * 256 + threadIdx.x;

    const float* p = g_pre + (size_t)b * T_ * H_ + h;

    float mem = 0.0f, adapt = 0.0f, cnt = 0.0f;
#pragma unroll 8
    for (int t = 0; t < T_; t++) {
        float v = p[(size_t)t * H_];
        mem = 0.9f * mem + v - adapt;
        float spk = (mem > 0.0f) ? 1.0f : 0.0f;
        adapt += 0.1f * spk;
        mem -= spk;
        cnt += spk;
    }

    float val = cnt * (1.0f / (float)T_) * W_out[h];

    __shared__ float red[256];
    red[threadIdx.x] = val;
    __syncthreads();
#pragma unroll
    for (int s = 128; s > 0; s >>= 1) {
        if (threadIdx.x < s) red[threadIdx.x] += red[threadIdx.x + s];
        __syncthreads();
    }
    if (threadIdx.x == 0) g_part[blockIdx.x] = red[0];
}

__global__ void finalize_kernel(const float* __restrict__ b_out, float* __restrict__ out) {
    int b = threadIdx.x;
    if (b < B_) {
        float s = g_part[b * 4 + 0] + g_part[b * 4 + 1] +
                  g_part[b * 4 + 2] + g_part[b * 4 + 3];
        out[b] = s + b_out[0];
    }
}

extern "C" void kernel_launch(void* const* d_in, const int* in_sizes, int n_in,
                              void* d_out, int out_size)
{
    (void)in_sizes; (void)n_in; (void)out_size;
    const float* x     = (const float*)d_in[0];  // [64,256,512]
    const float* W_in  = (const float*)d_in[1];  // [1024,512]
    const float* b_in  = (const float*)d_in[2];  // [1024]
    const float* W_out = (const float*)d_in[3];  // [1,1024]
    const float* b_out = (const float*)d_in[4];  // [1]
    float* out = (float*)d_out;                  // [64,1]

    split_kernel<<<(M_ * D_) / 4 / 256, 256>>>(x, 0);
    split_kernel<<<(H_ * D_) / 4 / 256, 256>>>(W_in, 1);

    dim3 ggrid(H_ / 128, M_ / 128);   // (8, 128)
    mma_gemm_kernel<<<ggrid, 256>>>(b_in);

    alif_scan_kernel<<<256, 256>>>(W_out);
    finalize_kernel<<<1, 64>>>(b_out, out);
}

// round 8
// speedup vs baseline: 1.1945x; 1.1945x over previous
#include <cuda_runtime.h>
#include <cstdint>

// Problem dims (fixed by the dataset)
#define B_  64
#define T_  256
#define D_  512
#define H_  1024
#define M_  (B_ * T_)   // 16384

// GEMM tiling
#define BM 128
#define BN 128
#define BK 8

// Scratch (allocation-free rule: __device__ globals)
__device__ float g_pre[(size_t)M_ * H_];   // 64 MB: pre-activations [m=b*T+t][h]
__device__ float g_part[256];

// ---------------------------------------------------------------------------
// Kernel 1: g_pre[m,n] = sum_k A[m,k] * W[n,k] + bias[n]
// 128x128x8 double-buffered SGEMM, 256 threads, 8x8 per-thread tile with 4+4
// split fragments. Inner product uses packed fma.rn.f32x2 (Blackwell FFMA2):
// accumulators paired over adjacent n, per-component RN => bitwise identical
// to the scalar-FFMA version (same per-accumulator k-ascending chain).
// ---------------------------------------------------------------------------
__global__ __launch_bounds__(256, 2) void gemm_bias_kernel(
    const float* __restrict__ A,
    const float* __restrict__ W,
    const float* __restrict__ bias)
{
    __shared__ float sA[2][BK][BM];
    __shared__ float sB[2][BK][BN];

    const int tid = threadIdx.x;
    const int bm = blockIdx.y * BM;
    const int bn = blockIdx.x * BN;

    // Global->smem load mapping: one float4 of A and one of W per thread per K-tile
    const int lrow = tid >> 1;        // 0..127
    const int lcol = (tid & 1) * 4;   // 0 or 4
    const float* Ap = A + (size_t)(bm + lrow) * D_ + lcol;
    const float* Wp = W + (size_t)(bn + lrow) * D_ + lcol;

    // Prime buffer 0
    {
        float4 a4 = *(const float4*)Ap;
        float4 w4 = *(const float4*)Wp;
        sA[0][lcol + 0][lrow] = a4.x; sA[0][lcol + 1][lrow] = a4.y;
        sA[0][lcol + 2][lrow] = a4.z; sA[0][lcol + 3][lrow] = a4.w;
        sB[0][lcol + 0][lrow] = w4.x; sB[0][lcol + 1][lrow] = w4.y;
        sB[0][lcol + 2][lrow] = w4.z; sB[0][lcol + 3][lrow] = w4.w;
    }
    __syncthreads();

    const int tx = tid & 15;   // n-direction, 16 threads
    const int ty = tid >> 4;   // m-direction, 16 threads

    // acc2[i][jp]: i = m-fragment row (0..7), jp = n-pair (0..3);
    // lo 32 bits = n=2*jp, hi = n=2*jp+1. 0ull == (0.0f, 0.0f).
    unsigned long long acc2[8][4];
#pragma unroll
    for (int i = 0; i < 8; i++)
#pragma unroll
        for (int jp = 0; jp < 4; jp++) acc2[i][jp] = 0ull;

    int buf = 0;
    for (int k0 = BK; k0 <= D_; k0 += BK) {
        const bool more = (k0 < D_);
        float4 na, nw;
        if (more) {
            na = *(const float4*)(Ap + k0);
            nw = *(const float4*)(Wp + k0);
        }
#pragma unroll
        for (int kk = 0; kk < BK; kk++) {
            float ra[8];
            unsigned long long rb2[4];
            *(float4*)&ra[0] = *(const float4*)&sA[buf][kk][ty * 4];
            *(float4*)&ra[4] = *(const float4*)&sA[buf][kk][64 + ty * 4];
            // B pairs read directly as packed 64-bit lanes (lo = lower n)
            *(ulonglong2*)&rb2[0] = *(const ulonglong2*)&sB[buf][kk][tx * 4];
            *(ulonglong2*)&rb2[2] = *(const ulonglong2*)&sB[buf][kk][64 + tx * 4];
#pragma unroll
            for (int i = 0; i < 8; i++) {
                unsigned long long a2;
                asm("mov.b64 %0, {%1, %1};" : "=l"(a2) : "f"(ra[i]));
#pragma unroll
                for (int jp = 0; jp < 4; jp++) {
                    asm("fma.rn.f32x2 %0, %1, %2, %0;"
                        : "+l"(acc2[i][jp])
                        : "l"(a2), "l"(rb2[jp]));
                }
            }
        }
        if (more) {
            buf ^= 1;
            sA[buf][lcol + 0][lrow] = na.x; sA[buf][lcol + 1][lrow] = na.y;
            sA[buf][lcol + 2][lrow] = na.z; sA[buf][lcol + 3][lrow] = na.w;
            sB[buf][lcol + 0][lrow] = nw.x; sB[buf][lcol + 1][lrow] = nw.y;
            sB[buf][lcol + 2][lrow] = nw.z; sB[buf][lcol + 3][lrow] = nw.w;
            __syncthreads();
        }
    }

    // Unpack accumulator pairs back to the scalar 8x8 view
    float acc[8][8];
#pragma unroll
    for (int i = 0; i < 8; i++)
#pragma unroll
        for (int jp = 0; jp < 4; jp++) {
            acc[i][2 * jp + 0] = __uint_as_float((uint32_t)(acc2[i][jp]));
            acc[i][2 * jp + 1] = __uint_as_float((uint32_t)(acc2[i][jp] >> 32));
        }

    // Epilogue: add bias, store (identical to the scalar version)
    float bs[8];
#pragma unroll
    for (int j = 0; j < 8; j++) {
        int n = bn + ((j < 4) ? (tx * 4 + j) : (64 + tx * 4 + (j - 4)));
        bs[j] = bias[n];
    }
#pragma unroll
    for (int i = 0; i < 8; i++) {
        int m = bm + ((i < 4) ? (ty * 4 + i) : (64 + ty * 4 + (i - 4)));
        float4 v0 = make_float4(acc[i][0] + bs[0], acc[i][1] + bs[1],
                                acc[i][2] + bs[2], acc[i][3] + bs[3]);
        float4 v1 = make_float4(acc[i][4] + bs[4], acc[i][5] + bs[5],
                                acc[i][6] + bs[6], acc[i][7] + bs[7]);
        *(float4*)&g_pre[(size_t)m * H_ + bn + tx * 4] = v0;
        *(float4*)&g_pre[(size_t)m * H_ + bn + 64 + tx * 4] = v1;
    }
}

// ---------------------------------------------------------------------------
// Kernel 2: ALIF recurrence over T per (b,h), then weighted partial reduce.
// ---------------------------------------------------------------------------
__global__ __launch_bounds__(256) void alif_scan_kernel(
    const float* __restrict__ W_out)
{
    const int b  = blockIdx.x >> 2;
    const int hc = blockIdx.x & 3;
    const int h  = hc * 256 + threadIdx.x;

    const float* p = g_pre + (size_t)b * T_ * H_ + h;

    float mem = 0.0f, adapt = 0.0f, cnt = 0.0f;
#pragma unroll 8
    for (int t = 0; t < T_; t++) {
        float v = p[(size_t)t * H_];
        mem = 0.9f * mem + v - adapt;
        float spk = (mem > 0.0f) ? 1.0f : 0.0f;
        adapt += 0.1f * spk;
        mem -= spk;
        cnt += spk;
    }

    float val = cnt * (1.0f / (float)T_) * W_out[h];

    __shared__ float red[256];
    red[threadIdx.x] = val;
    __syncthreads();
#pragma unroll
    for (int s = 128; s > 0; s >>= 1) {
        if (threadIdx.x < s) red[threadIdx.x] += red[threadIdx.x + s];
        __syncthreads();
    }
    if (threadIdx.x == 0) g_part[blockIdx.x] = red[0];
}

// ---------------------------------------------------------------------------
// Kernel 3: out[b] = sum_c g_part[b*4+c] + b_out[0]
// ---------------------------------------------------------------------------
__global__ void finalize_kernel(const float* __restrict__ b_out,
                                float* __restrict__ out)
{
    int b = threadIdx.x;
    if (b < B_) {
        float s = g_part[b * 4 + 0] + g_part[b * 4 + 1] +
                  g_part[b * 4 + 2] + g_part[b * 4 + 3];
        out[b] = s + b_out[0];
    }
}

extern "C" void kernel_launch(void* const* d_in, const int* in_sizes, int n_in,
                              void* d_out, int out_size)
{
    (void)in_sizes; (void)n_in; (void)out_size;
    const float* x     = (const float*)d_in[0];  // [64,256,512]
    const float* W_in  = (const float*)d_in[1];  // [1024,512]
    const float* b_in  = (const float*)d_in[2];  // [1024]
    const float* W_out = (const float*)d_in[3];  // [1,1024]
    const float* b_out = (const float*)d_in[4];  // [1]
    float* out = (float*)d_out;                  // [64,1]

    dim3 ggrid(H_ / BN, M_ / BM);     // (8, 128)
    gemm_bias_kernel<<<ggrid, 256>>>(x, W_in, b_in);
    alif_scan_kernel<<<256, 256>>>(W_out);
    finalize_kernel<<<1, 64>>>(b_out, out);
}